// round 14
// baseline (speedup 1.0000x reference)
#include <cuda_runtime.h>
#include <cuda_bf16.h>
#include <math.h>

#define NB 32
#define CI 8
#define CO 8
#define KR 4
#define DI 16
#define DOUT 16
#define SS 32
#define NPIX 1024
#define PLANE (DOUT*NPIX)   // 16384

#define KSP 288             // packed operand width: [hi 144 | lo 144] bf16
#define AB_ST 152           // smem row stride bf16 (76 words = 12 mod 32 -> conflict-free)

#define S2ST 35             // K2 smem row stride
#define S2PL (34*S2ST)      // 1190
#define S2CH (6*S2PL)       // 7140

typedef unsigned long long u64;
typedef unsigned int u32;

// ---------------- scratch (static device globals; no allocation) -------------
__device__ float g_pooled[NB*CO*2*PLANE];    // 33.5 MB
__device__ float g_preroute[NB*CO*PLANE];    // 16.8 MB
__device__ float g_gate[NB*CO*PLANE];        // 16.8 MB
__device__ float g_votes[NB*CO*128*NPIX];    // [b][o][d][ci][pix] 134 MB
__device__ double g_part2[2*CO*NB*4];        // BN partials per (o,b,dz)
__device__ __nv_bfloat16 g_X2[NB*NPIX*KSP];  // [b][pix][Xh|Xl]  18.9 MB
__device__ __nv_bfloat16 g_W2[CO*128*KSP];   // [o][m][Wh|Wl]

// ---------------- helpers ----------------------------------------------------
__device__ __forceinline__ void ffma2(u64& d, const u64 a, const u64 b) {
    asm("fma.rn.f32x2 %0, %1, %2, %0;" : "+l"(d) : "l"(a), "l"(b));
}
__device__ __forceinline__ u64 pack2(float x, float y) {
    u64 r; asm("mov.b64 %0, {%1,%2};" : "=l"(r) : "f"(x), "f"(y)); return r;
}
__device__ __forceinline__ float2 unpack2(u64 v) {
    float2 r; asm("mov.b64 {%0,%1}, %2;" : "=f"(r.x), "=f"(r.y) : "l"(v)); return r;
}
__device__ __forceinline__ void mma_bf16(float* d, const u32* a, const u32* b) {
    asm volatile(
        "mma.sync.aligned.m16n8k16.row.col.f32.bf16.bf16.f32 "
        "{%0,%1,%2,%3}, {%4,%5,%6,%7}, {%8,%9}, {%0,%1,%2,%3};"
        : "+f"(d[0]), "+f"(d[1]), "+f"(d[2]), "+f"(d[3])
        : "r"(a[0]), "r"(a[1]), "r"(a[2]), "r"(a[3]), "r"(b[0]), "r"(b[1]));
}
__device__ __forceinline__ void ldsm_x4(u32& r0, u32& r1, u32& r2, u32& r3, u32 addr) {
    asm volatile("ldmatrix.sync.aligned.m8n8.x4.shared.b16 {%0,%1,%2,%3}, [%4];"
                 : "=r"(r0), "=r"(r1), "=r"(r2), "=r"(r3) : "r"(addr));
}
__device__ __forceinline__ u32 s2u(const void* p) {
    return (u32)__cvta_generic_to_shared(p);
}

// ---------------------------------------------------------------------------
// K0: build bf16 split operands.  blocks 0..31: X for batch b; block 32: W.
// ---------------------------------------------------------------------------
extern "C" __global__ void __launch_bounds__(1024)
k0_prep(const float* __restrict__ caps, const float* __restrict__ Wt)
{
    extern __shared__ float sp[];   // 16*34*34 = 18496
    const int tid = threadIdx.x;
    if (blockIdx.x < NB) {
        const int b = blockIdx.x;
        for (int idx = tid; idx < DI*1156; idx += 1024) {
            int ch = idx / 1156, rem = idx % 1156;
            int pr = rem / 34, pc = rem % 34;
            float v = 0.f;
            if (pr >= 1 && pr <= SS && pc >= 1 && pc <= SS)
                v = caps[((b*DI + ch)*SS + (pr-1))*SS + (pc-1)];
            sp[idx] = v;
        }
        __syncthreads();
        for (int idx = tid; idx < NPIX*144; idx += 1024) {
            int pix = idx / 144, s = idx % 144;
            int cin = s / 9, tap = s % 9;
            int dy = tap / 3, dx = tap % 3;
            int prow = pix >> 5, pcol = pix & 31;
            float v = sp[cin*1156 + (prow+dy)*34 + (pcol+dx)];
            __nv_bfloat16 h = __float2bfloat16(v);
            __nv_bfloat16 l = __float2bfloat16(v - __bfloat162float(h));
            __nv_bfloat16* dst = g_X2 + (pix + (u64)b*NPIX)*KSP + s;
            dst[0]   = h;      // Xh
            dst[144] = l;      // Xl
        }
    } else {
        for (int idx = tid; idx < CO*128*144; idx += 1024) {
            int s = idx % 144, m = (idx/144) & 127, o = idx/(144*128);
            int c = m >> 4, d = m & 15;
            float v = Wt[(((c*CO + o)*DOUT + d)*144) + s];
            __nv_bfloat16 h = __float2bfloat16(v);
            __nv_bfloat16 l = __float2bfloat16(v - __bfloat162float(h));
            __nv_bfloat16* dst = g_W2 + (o*128 + m)*KSP + s;
            dst[0]   = h;      // Wh
            dst[144] = l;      // Wl
        }
    }
}

// ---------------------------------------------------------------------------
// K1a: bf16 3-term split conv-GEMM, block tile 128m x 64pix, K=144/term.
// grid (o=8, b=32, pt=16), 256 threads (8 warps = 4m x 2n, warp tile 32x32),
// 58.4 KB smem -> 3 blocks/SM.  Fragments via ldmatrix.x4.
// Writes raw votes (no bias) from accum regs, coalesced STG.64.
// ---------------------------------------------------------------------------
extern "C" __global__ void __launch_bounds__(256, 3)
k1a_gemm()
{
    extern __shared__ float sm[];
    __nv_bfloat16* s_A = (__nv_bfloat16*)sm;           // 128 x AB_ST
    __nv_bfloat16* s_B = s_A + 128*AB_ST;              // 64 x AB_ST

    const int o = blockIdx.x, b = blockIdx.y, pt = blockIdx.z;
    const int tb = pt*64;
    const int tid  = threadIdx.x;
    const int w    = tid >> 5, lane = tid & 31;
    const int wm   = w & 3,  wn = w >> 2;       // warp tile: rows wm*32, cols wn*32
    const int g    = lane >> 2, t = lane & 3;
    const int lm   = lane >> 3, lr = lane & 7;  // ldmatrix lane decomposition
    const int obase = b*CO + o;

    // ldmatrix base addresses (byte offsets move with kb*2 inside loop)
    u32 a_base[2], b_base[2];
    #pragma unroll
    for (int mi = 0; mi < 2; mi++)
        a_base[mi] = s2u(s_A + (wm*32 + mi*16 + (lm & 1)*8 + lr)*AB_ST + (lm >> 1)*8);
    #pragma unroll
    for (int p = 0; p < 2; p++)
        b_base[p] = s2u(s_B + (wn*32 + p*16 + (lm >> 1)*8 + lr)*AB_ST + (lm & 1)*8);

    float acc[2][4][4];
    #pragma unroll
    for (int mi = 0; mi < 2; mi++)
        #pragma unroll
        for (int nj = 0; nj < 4; nj++)
            #pragma unroll
            for (int e = 0; e < 4; e++) acc[mi][nj][e] = 0.f;

    // segs: (aoff, boff, stageA, stageB): (144,0,1,1), (0,0,1,0), (0,144,0,1)
    #pragma unroll 1
    for (int seg = 0; seg < 3; seg++) {
        const int aoff = (seg == 0) ? 144 : 0;
        const int boff = (seg == 2) ? 144 : 0;
        const bool stA = (seg < 2), stB = (seg != 1);
        if (stA) {
            #pragma unroll
            for (int i = tid; i < 2304; i += 256) {
                int m = i / 18, j = i % 18;
                float4 v = ((const float4*)(g_W2 + (o*128 + m)*KSP + aoff))[j];
                ((float4*)((char*)s_A + m*(AB_ST*2)))[j] = v;
            }
        }
        if (stB) {
            #pragma unroll
            for (int i = tid; i < 1152; i += 256) {
                int pr = i / 18, j = i % 18;
                float4 v = ((const float4*)(g_X2 + ((u64)b*NPIX + tb + pr)*KSP + boff))[j];
                ((float4*)((char*)s_B + pr*(AB_ST*2)))[j] = v;
            }
        }
        __syncthreads();
        #pragma unroll
        for (int ks = 0; ks < 9; ks++) {
            const int kbb = ks*32;   // byte offset (16 bf16 = 32B)
            u32 afr[2][4];
            #pragma unroll
            for (int mi = 0; mi < 2; mi++)
                ldsm_x4(afr[mi][0], afr[mi][1], afr[mi][2], afr[mi][3],
                        a_base[mi] + kbb);
            u32 bfr[4][2];
            #pragma unroll
            for (int p = 0; p < 2; p++)
                ldsm_x4(bfr[p*2][0], bfr[p*2][1], bfr[p*2+1][0], bfr[p*2+1][1],
                        b_base[p] + kbb);
            #pragma unroll
            for (int mi = 0; mi < 2; mi++)
                #pragma unroll
                for (int nj = 0; nj < 4; nj++)
                    mma_bf16(acc[mi][nj], afr[mi], bfr[nj]);
        }
        __syncthreads();
    }

    // write raw votes from regs: [b][o][d][ci][pix], STG.64 (pix pairs)
    #pragma unroll
    for (int mi = 0; mi < 2; mi++) {
        #pragma unroll
        for (int e2 = 0; e2 < 2; e2++) {
            int m = wm*32 + mi*16 + g + e2*8;
            int ci = m >> 4, d = m & 15;
            float* rowp = g_votes + (((u64)obase*16 + d)*8 + ci)*NPIX;
            #pragma unroll
            for (int nj = 0; nj < 4; nj++) {
                int pix = tb + wn*32 + nj*8 + 2*t;
                u64 v = pack2(acc[mi][nj][e2*2], acc[mi][nj][e2*2+1]);
                *(u64*)(rowp + pix) = v;
            }
        }
    }
}

// ---------------------------------------------------------------------------
// K1b: routing epilogue (+conv bias).  grid (o=8, b=32, pz=4), 256 threads.
// ---------------------------------------------------------------------------
extern "C" __global__ void __launch_bounds__(256)
k1b_route(const float* __restrict__ bt, const float* __restrict__ Wv,
          const float* __restrict__ bv)
{
    __shared__ u64 s_wp[128];
    __shared__ u64 s_bvp[16];
    __shared__ float s_bt[128];
    const int o = blockIdx.x, b = blockIdx.y, pz = blockIdx.z;
    const int tid = threadIdx.x;
    const int obase = b*CO + o;

    if (tid < 128) {
        int c2 = tid >> 4, ci = (tid >> 1) & 7, h = tid & 1;
        s_wp[tid] = pack2(Wv[o*256 + ((2*h)*8 + c2)*8 + ci],
                          Wv[o*256 + ((2*h+1)*8 + c2)*8 + ci]);
        s_bt[tid] = bt[(((tid >> 4)*CO + o)*DOUT) + (tid & 15)];
    }
    if (tid < 16) {
        int c2 = tid >> 1, h = tid & 1;
        s_bvp[tid] = pack2(bv[o*32 + (2*h)*8 + c2], bv[o*32 + (2*h+1)*8 + c2]);
    }
    __syncthreads();

    #pragma unroll 1
    for (int i = 0; i < 16; i++) {
        int idx = i*256 + tid;           // 0..4095
        int pix = pz*256 + (idx & 255);
        int d   = idx >> 8;
        const float* vb = g_votes + ((u64)obase*16 + d)*8*NPIX + pix;
        const float* sb = s_bt + d;
        u64 vd[8];
        #pragma unroll
        for (int ci = 0; ci < 8; ci++) {
            float v = vb[ci*NPIX] + sb[ci*16];
            vd[ci] = pack2(v, v);
        }
        float vmax = -3.0e38f, vsum = 0.f, num = 0.f, den = 0.f;
        #pragma unroll
        for (int c2 = 0; c2 < 8; c2++) {
            u64 a0 = s_bvp[c2*2 + 0];
            u64 a1 = s_bvp[c2*2 + 1];
            #pragma unroll
            for (int ci = 0; ci < 8; ci++) {
                ffma2(a0, vd[ci], s_wp[(c2*8 + ci)*2 + 0]);
                ffma2(a1, vd[ci], s_wp[(c2*8 + ci)*2 + 1]);
            }
            float2 p0 = unpack2(a0), p1 = unpack2(a1);
            float v0 = p0.x, v1 = p0.y, v2 = p1.x, v3 = p1.y;
            vmax = fmaxf(vmax, fmaxf(fmaxf(v0, v1), fmaxf(v2, v3)));
            float sum4 = (v0 + v1) + (v2 + v3);
            vsum += sum4;
            float mu = 0.25f*sum4;
            float d0 = v0-mu, d1 = v1-mu, d2 = v2-mu, d3 = v3-mu;
            float var = 0.25f*((d0*d0 + d1*d1) + (d2*d2 + d3*d3));
            float rr = rsqrtf(var);
            num += rr*mu;
            den += rr;
        }
        g_pooled[(obase*2 + 0)*PLANE + d*NPIX + pix] = vmax;
        g_pooled[(obase*2 + 1)*PLANE + d*NPIX + pix] = vsum*(1.f/32.f);
        g_preroute[obase*PLANE + d*NPIX + pix] = num/den;
    }
}

// ---------------------------------------------------------------------------
// K2: spatial gate 3x3x3 conv + BN partials, d-tiled, stride 35,
// shift-indexed staging.  grid (o=8, b=32, dz=4), 256 threads.
// ---------------------------------------------------------------------------
extern "C" __global__ void __launch_bounds__(256, 4)
k2_gate(const float* __restrict__ Ws)
{
    extern __shared__ float sp[];  // [2][6][34][35] = 14280 floats
    __shared__ float s_ws[54];
    __shared__ double s_redA[8], s_redB[8];

    const int o = blockIdx.x, b = blockIdx.y, dz = blockIdx.z;
    const int tid = threadIdx.x;
    const int obase = b*CO + o;

    if (tid < 54) s_ws[tid] = Ws[tid];
    for (int idx = tid; idx < 2*S2CH; idx += 256) sp[idx] = 0.f;
    __syncthreads();
    #pragma unroll 1
    for (int ch = 0; ch < 2; ch++) {
        #pragma unroll 1
        for (int dd = 0; dd < 6; dd++) {
            int dg = dz*4 + dd - 1;
            if (dg < 0 || dg > 15) continue;
            const float* src = g_pooled + (obase*2 + ch)*PLANE + dg*NPIX;
            float* dstp = sp + ch*S2CH + dd*S2PL + S2ST + 1;
            #pragma unroll
            for (int idx = tid; idx < 1024; idx += 256) {
                int r2 = idx >> 5, cc = idx & 31;
                dstp[r2*S2ST + cc] = src[idx];
            }
        }
    }
    __syncthreads();

    const int dl = tid >> 6;
    const int u  = (tid >> 1) & 31;
    const int vh = (tid & 1) * 16;
    float acc[16];
    #pragma unroll
    for (int v = 0; v < 16; v++) acc[v] = 0.f;
    #pragma unroll 1
    for (int ch = 0; ch < 2; ch++) {
        #pragma unroll
        for (int kd = 0; kd < 3; kd++) {
            #pragma unroll
            for (int kh = 0; kh < 3; kh++) {
                const float* xr = sp + ch*S2CH + (dl+kd)*S2PL + (u+kh)*S2ST + vh;
                float xx[18];
                #pragma unroll
                for (int j = 0; j < 18; j++) xx[j] = xr[j];
                const float* wp = s_ws + ch*27 + kd*9 + kh*3;
                float w0 = wp[0], w1 = wp[1], w2 = wp[2];
                #pragma unroll
                for (int v = 0; v < 16; v++)
                    acc[v] += w0*xx[v] + w1*xx[v+1] + w2*xx[v+2];
            }
        }
    }
    double s = 0.0, s2 = 0.0;
    float* gout = g_gate + obase*PLANE + (dz*4 + dl)*NPIX + u*32 + vh;
    #pragma unroll
    for (int v = 0; v < 16; v++) {
        gout[v] = acc[v];
        double dv = (double)acc[v];
        s += dv; s2 += dv*dv;
    }
    #pragma unroll
    for (int off = 16; off > 0; off >>= 1) {
        s  += __shfl_down_sync(0xffffffffu, s,  off);
        s2 += __shfl_down_sync(0xffffffffu, s2, off);
    }
    int w = tid >> 5;
    if ((tid & 31) == 0) { s_redA[w] = s; s_redB[w] = s2; }
    __syncthreads();
    if (tid < 32) {
        double a = (tid < 8) ? s_redA[tid] : 0.0;
        double bq = (tid < 8) ? s_redB[tid] : 0.0;
        #pragma unroll
        for (int off = 4; off > 0; off >>= 1) {
            a  += __shfl_down_sync(0xffffffffu, a,  off);
            bq += __shfl_down_sync(0xffffffffu, bq, off);
        }
        if (tid == 0) {
            g_part2[(o*NB + b)*4 + dz] = a;
            g_part2[CO*NB*4 + (o*NB + b)*4 + dz] = bq;
        }
    }
}

// ---------------------------------------------------------------------------
// K3: BN-affine (from g_part2) + (1+sigmoid)*preroute + LayerNorm
// ---------------------------------------------------------------------------
extern "C" __global__ void __launch_bounds__(512)
k3_finalize(const float* __restrict__ bng, const float* __restrict__ bnb,
            const float* __restrict__ lng, const float* __restrict__ lnb,
            float* __restrict__ out)
{
    __shared__ float s_red[16];
    __shared__ float sh_a, sh_ofs;
    const int o = blockIdx.x, b = blockIdx.y;
    const int tid = threadIdx.x;
    const int base = (b*CO + o)*PLANE;

    if (tid < 32) {
        double s = 0.0, s2 = 0.0;
        #pragma unroll
        for (int j = 0; j < 4; j++) {
            s  += g_part2[o*NB*4 + tid*4 + j];
            s2 += g_part2[CO*NB*4 + o*NB*4 + tid*4 + j];
        }
        #pragma unroll
        for (int off = 16; off > 0; off >>= 1) {
            s  += __shfl_down_sync(0xffffffffu, s,  off);
            s2 += __shfl_down_sync(0xffffffffu, s2, off);
        }
        if (tid == 0) {
            double n = (double)NB * PLANE;
            double mu = s / n;
            double var = s2 / n - mu*mu;
            float rstd = (float)(1.0 / sqrt(var + 1e-5));
            float a = bng[0] * rstd;
            sh_a = a;
            sh_ofs = bnb[0] - (float)mu * a;
        }
    }
    __syncthreads();
    const float a = sh_a, ofs = sh_ofs;

    float x[32];
    float s = 0.f;
    #pragma unroll
    for (int i = 0; i < 32; i++) {
        int idx = tid + i*512;
        float g = g_gate[base + idx];
        float z = g*a + ofs;
        float sg = 1.f / (1.f + expf(-z));
        float val = g_preroute[base + idx] * (1.f + sg);
        x[i] = val; s += val;
    }
    #pragma unroll
    for (int off = 16; off > 0; off >>= 1) s += __shfl_down_sync(0xffffffffu, s, off);
    int w = tid >> 5;
    if ((tid & 31) == 0) s_red[w] = s;
    __syncthreads();
    if (tid < 32) {
        float t = (tid < 16) ? s_red[tid] : 0.f;
        #pragma unroll
        for (int off = 8; off > 0; off >>= 1) t += __shfl_down_sync(0xffffffffu, t, off);
        if (tid == 0) s_red[0] = t;
    }
    __syncthreads();
    float m = s_red[0] * (1.f/16384.f);
    __syncthreads();

    float v = 0.f;
    #pragma unroll
    for (int i = 0; i < 32; i++) { float dd = x[i] - m; v += dd*dd; }
    #pragma unroll
    for (int off = 16; off > 0; off >>= 1) v += __shfl_down_sync(0xffffffffu, v, off);
    if ((tid & 31) == 0) s_red[w] = v;
    __syncthreads();
    if (tid < 32) {
        float t = (tid < 16) ? s_red[tid] : 0.f;
        #pragma unroll
        for (int off = 8; off > 0; off >>= 1) t += __shfl_down_sync(0xffffffffu, t, off);
        if (tid == 0) s_red[0] = t;
    }
    __syncthreads();
    float rstd = rsqrtf(s_red[0]*(1.f/16384.f) + 1e-5f);

    float* op = out + (o*NB + b)*PLANE;
    #pragma unroll
    for (int i = 0; i < 32; i++) {
        int idx = tid + i*512;
        op[idx] = (x[i] - m)*rstd*lng[idx] + lnb[idx];
    }
}

// ---------------------------------------------------------------------------
extern "C" void kernel_launch(void* const* d_in, const int* in_sizes, int n_in,
                              void* d_out, int out_size)
{
    const float* caps = (const float*)d_in[0];
    const float* Wt   = (const float*)d_in[1];
    const float* bt   = (const float*)d_in[2];
    const float* Wv   = (const float*)d_in[3];
    const float* bv   = (const float*)d_in[4];
    const float* Ws   = (const float*)d_in[5];
    const float* bng  = (const float*)d_in[6];
    const float* bnb  = (const float*)d_in[7];
    const float* lng  = (const float*)d_in[8];
    const float* lnb  = (const float*)d_in[9];
    float* out = (float*)d_out;

    const int smem0  = DI*34*34 * 4;               // 73984
    const int smem1a = (128 + 64)*AB_ST*2;         // 58368
    const int smem2  = 2*S2CH * 4;                 // 57120
    cudaFuncSetAttribute(k0_prep,  cudaFuncAttributeMaxDynamicSharedMemorySize, smem0);
    cudaFuncSetAttribute(k1a_gemm, cudaFuncAttributeMaxDynamicSharedMemorySize, smem1a);
    cudaFuncSetAttribute(k2_gate,  cudaFuncAttributeMaxDynamicSharedMemorySize, smem2);

    k0_prep<<<NB + 1, 1024, smem0>>>(caps, Wt);
    k1a_gemm<<<dim3(CO, NB, 16), 256, smem1a>>>();
    k1b_route<<<dim3(CO, NB, 4), 256>>>(bt, Wv, bv);
    k2_gate<<<dim3(CO, NB, 4), 256, smem2>>>(Ws);
    k3_finalize<<<dim3(CO, NB), 512>>>(bng, bnb, lng, lnb, out);
}

// round 15
// speedup vs baseline: 1.1254x; 1.1254x over previous
#include <cuda_runtime.h>
#include <cuda_fp16.h>
#include <math.h>

#define NB 32
#define CI 8
#define CO 8
#define KR 4
#define DI 16
#define DOUT 16
#define SS 32
#define NPIX 1024
#define PLANE (DOUT*NPIX)   // 16384

#define AB_ST 152           // smem row stride (halves); 76 words = 12 mod 32 -> conflict-free

#define S2ST 35             // K2 smem row stride
#define S2PL (34*S2ST)      // 1190
#define S2CH (6*S2PL)       // 7140

typedef unsigned long long u64;
typedef unsigned int u32;

// ---------------- scratch (static device globals; no allocation) -------------
__device__ float g_pooled[NB*CO*2*PLANE];    // 33.5 MB
__device__ float g_preroute[NB*CO*PLANE];    // 16.8 MB
__device__ float g_gate[NB*CO*PLANE];        // 16.8 MB
__device__ float g_votes[NB*CO*128*NPIX];    // [b][o][d][ci][pix] 134 MB
__device__ double g_part2[2*CO*NB*4];        // BN partials per (o,b,dz)
__device__ __half g_Xh[NB*NPIX*144];         // [b][pix][Xh]  9.4 MB
__device__ __half g_W2[CO*128*288];          // [o][m][Wh(144)|Wl(144)]

// ---------------- helpers ----------------------------------------------------
__device__ __forceinline__ void ffma2(u64& d, const u64 a, const u64 b) {
    asm("fma.rn.f32x2 %0, %1, %2, %0;" : "+l"(d) : "l"(a), "l"(b));
}
__device__ __forceinline__ u64 pack2(float x, float y) {
    u64 r; asm("mov.b64 %0, {%1,%2};" : "=l"(r) : "f"(x), "f"(y)); return r;
}
__device__ __forceinline__ float2 unpack2(u64 v) {
    float2 r; asm("mov.b64 {%0,%1}, %2;" : "=f"(r.x), "=f"(r.y) : "l"(v)); return r;
}
__device__ __forceinline__ void mma_f16(float* d, const u32* a, const u32* b) {
    asm volatile(
        "mma.sync.aligned.m16n8k16.row.col.f32.f16.f16.f32 "
        "{%0,%1,%2,%3}, {%4,%5,%6,%7}, {%8,%9}, {%0,%1,%2,%3};"
        : "+f"(d[0]), "+f"(d[1]), "+f"(d[2]), "+f"(d[3])
        : "r"(a[0]), "r"(a[1]), "r"(a[2]), "r"(a[3]), "r"(b[0]), "r"(b[1]));
}

// ---------------------------------------------------------------------------
// K0: build fp16 split operands.  blocks 0..31: X for batch b; block 32: W.
// X: hi only (2-term split uses Xh for both GEMM terms).  W: [Wh|Wl].
// ---------------------------------------------------------------------------
extern "C" __global__ void __launch_bounds__(1024)
k0_prep(const float* __restrict__ caps, const float* __restrict__ Wt)
{
    extern __shared__ float sp[];   // 16*34*34 = 18496
    const int tid = threadIdx.x;
    if (blockIdx.x < NB) {
        const int b = blockIdx.x;
        for (int idx = tid; idx < DI*1156; idx += 1024) {
            int ch = idx / 1156, rem = idx % 1156;
            int pr = rem / 34, pc = rem % 34;
            float v = 0.f;
            if (pr >= 1 && pr <= SS && pc >= 1 && pc <= SS)
                v = caps[((b*DI + ch)*SS + (pr-1))*SS + (pc-1)];
            sp[idx] = v;
        }
        __syncthreads();
        for (int idx = tid; idx < NPIX*144; idx += 1024) {
            int pix = idx / 144, s = idx % 144;
            int cin = s / 9, tap = s % 9;
            int dy = tap / 3, dx = tap % 3;
            int prow = pix >> 5, pcol = pix & 31;
            float v = sp[cin*1156 + (prow+dy)*34 + (pcol+dx)];
            g_Xh[((u64)b*NPIX + pix)*144 + s] = __float2half(v);
        }
    } else {
        for (int idx = tid; idx < CO*128*144; idx += 1024) {
            int s = idx % 144, m = (idx/144) & 127, o = idx/(144*128);
            int c = m >> 4, d = m & 15;
            float v = Wt[(((c*CO + o)*DOUT + d)*144) + s];
            __half h = __float2half(v);
            __half l = __float2half(v - __half2float(h));
            __half* dst = g_W2 + (o*128 + m)*288 + s;
            dst[0]   = h;      // Wh
            dst[144] = l;      // Wl
        }
    }
}

// ---------------------------------------------------------------------------
// K1a: fp16 2-term split conv-GEMM (Wh*Xh + Wl*Xh), tile 128m x 128pix,
// K=144/term.  grid (o=8, b=32, pt=8), 256 threads, 78.3 KB smem,
// 2 blocks/SM.  B (Xh) staged once per tile; A staged per term.
// Writes votes (+bias) straight from accum regs, coalesced STG.64.
// ---------------------------------------------------------------------------
extern "C" __global__ void __launch_bounds__(256, 2)
k1a_gemm(const float* __restrict__ bt)
{
    extern __shared__ float sm[];
    float* s_bias = sm;                        // 128 floats
    __half* s_A = (__half*)(sm + 128);         // 128 x AB_ST
    __half* s_B = s_A + 128*AB_ST;             // 128 x AB_ST

    const int o = blockIdx.x, b = blockIdx.y, pt = blockIdx.z;
    const int tb = pt*128;
    const int tid  = threadIdx.x;
    const int w    = tid >> 5, lane = tid & 31;
    const int wm   = w & 3,  wn = w >> 2;       // warp tile: rows wm*32, cols wn*64
    const int g    = lane >> 2, t = lane & 3;
    const int obase = b*CO + o;

    if (tid < 128)
        s_bias[tid] = bt[(((tid >> 4)*CO + o)*DOUT) + (tid & 15)];

    float acc[2][8][4];
    #pragma unroll
    for (int mi = 0; mi < 2; mi++)
        #pragma unroll
        for (int nj = 0; nj < 8; nj++)
            #pragma unroll
            for (int e = 0; e < 4; e++) acc[mi][nj][e] = 0.f;

    #pragma unroll 1
    for (int seg = 0; seg < 2; seg++) {
        const int aoff = seg*144;              // Wh then Wl
        // stage A: 128 rows x 18 float4 (144 fp16/row)
        #pragma unroll
        for (int i = tid; i < 2304; i += 256) {
            int m = i / 18, j = i % 18;
            float4 v = ((const float4*)(g_W2 + (o*128 + m)*288 + aoff))[j];
            ((float4*)((char*)s_A + m*(AB_ST*2)))[j] = v;
        }
        // stage B once (seg 0): 128 rows x 18 float4
        if (seg == 0) {
            #pragma unroll
            for (int i = tid; i < 2304; i += 256) {
                int pr = i / 18, j = i % 18;
                float4 v = ((const float4*)(g_Xh + ((u64)b*NPIX + tb + pr)*144))[j];
                ((float4*)((char*)s_B + pr*(AB_ST*2)))[j] = v;
            }
        }
        __syncthreads();
        // 9 k16-steps
        #pragma unroll
        for (int ks = 0; ks < 9; ks++) {
            const int kb = ks*16;    // fp16 units
            u32 afr[2][4];
            #pragma unroll
            for (int mi = 0; mi < 2; mi++) {
                const __half* ar = s_A + (wm*32 + mi*16 + g)*AB_ST + kb + 2*t;
                afr[mi][0] = *(const u32*)(ar);
                afr[mi][1] = *(const u32*)(ar + 8*AB_ST);
                afr[mi][2] = *(const u32*)(ar + 8);
                afr[mi][3] = *(const u32*)(ar + 8*AB_ST + 8);
            }
            u32 bfr[8][2];
            #pragma unroll
            for (int nj = 0; nj < 8; nj++) {
                const __half* br = s_B + (wn*64 + nj*8 + g)*AB_ST + kb + 2*t;
                bfr[nj][0] = *(const u32*)(br);
                bfr[nj][1] = *(const u32*)(br + 8);
            }
            #pragma unroll
            for (int mi = 0; mi < 2; mi++)
                #pragma unroll
                for (int nj = 0; nj < 8; nj++)
                    mma_f16(acc[mi][nj], afr[mi], bfr[nj]);
        }
        __syncthreads();
    }

    // write votes (+bias) from regs: [b][o][d][ci][pix], STG.64 (pix pairs)
    #pragma unroll
    for (int mi = 0; mi < 2; mi++) {
        #pragma unroll
        for (int e2 = 0; e2 < 2; e2++) {
            int m = wm*32 + mi*16 + g + e2*8;
            int ci = m >> 4, d = m & 15;
            float bias = s_bias[m];
            float* rowp = g_votes + (((u64)obase*16 + d)*8 + ci)*NPIX;
            #pragma unroll
            for (int nj = 0; nj < 8; nj++) {
                int pix = tb + wn*64 + nj*8 + 2*t;
                u64 v = pack2(acc[mi][nj][e2*2] + bias, acc[mi][nj][e2*2+1] + bias);
                *(u64*)(rowp + pix) = v;
            }
        }
    }
}

// ---------------------------------------------------------------------------
// K1b: routing epilogue.  grid (o=8, b=32, pz=4), 256 threads.
// ---------------------------------------------------------------------------
extern "C" __global__ void __launch_bounds__(256)
k1b_route(const float* __restrict__ Wv, const float* __restrict__ bv)
{
    __shared__ u64 s_wp[128];
    __shared__ u64 s_bvp[16];
    const int o = blockIdx.x, b = blockIdx.y, pz = blockIdx.z;
    const int tid = threadIdx.x;
    const int obase = b*CO + o;

    if (tid < 128) {
        int c2 = tid >> 4, ci = (tid >> 1) & 7, h = tid & 1;
        s_wp[tid] = pack2(Wv[o*256 + ((2*h)*8 + c2)*8 + ci],
                          Wv[o*256 + ((2*h+1)*8 + c2)*8 + ci]);
    }
    if (tid < 16) {
        int c2 = tid >> 1, h = tid & 1;
        s_bvp[tid] = pack2(bv[o*32 + (2*h)*8 + c2], bv[o*32 + (2*h+1)*8 + c2]);
    }
    __syncthreads();

    #pragma unroll 1
    for (int i = 0; i < 16; i++) {
        int idx = i*256 + tid;           // 0..4095
        int pix = pz*256 + (idx & 255);
        int d   = idx >> 8;
        const float* vb = g_votes + ((u64)obase*16 + d)*8*NPIX + pix;
        u64 vd[8];
        #pragma unroll
        for (int ci = 0; ci < 8; ci++) {
            float v = vb[ci*NPIX];
            vd[ci] = pack2(v, v);
        }
        float vmax = -3.0e38f, vsum = 0.f, num = 0.f, den = 0.f;
        #pragma unroll
        for (int c2 = 0; c2 < 8; c2++) {
            u64 a0 = s_bvp[c2*2 + 0];
            u64 a1 = s_bvp[c2*2 + 1];
            #pragma unroll
            for (int ci = 0; ci < 8; ci++) {
                ffma2(a0, vd[ci], s_wp[(c2*8 + ci)*2 + 0]);
                ffma2(a1, vd[ci], s_wp[(c2*8 + ci)*2 + 1]);
            }
            float2 p0 = unpack2(a0), p1 = unpack2(a1);
            float v0 = p0.x, v1 = p0.y, v2 = p1.x, v3 = p1.y;
            vmax = fmaxf(vmax, fmaxf(fmaxf(v0, v1), fmaxf(v2, v3)));
            float sum4 = (v0 + v1) + (v2 + v3);
            vsum += sum4;
            float mu = 0.25f*sum4;
            float d0 = v0-mu, d1 = v1-mu, d2 = v2-mu, d3 = v3-mu;
            float var = 0.25f*((d0*d0 + d1*d1) + (d2*d2 + d3*d3));
            float rr = rsqrtf(var);
            num += rr*mu;
            den += rr;
        }
        g_pooled[(obase*2 + 0)*PLANE + d*NPIX + pix] = vmax;
        g_pooled[(obase*2 + 1)*PLANE + d*NPIX + pix] = vsum*(1.f/32.f);
        g_preroute[obase*PLANE + d*NPIX + pix] = num/den;
    }
}

// ---------------------------------------------------------------------------
// K2: spatial gate 3x3x3 conv + BN partials, d-tiled, stride 35,
// shift-indexed staging.  grid (o=8, b=32, dz=4), 256 threads.
// ---------------------------------------------------------------------------
extern "C" __global__ void __launch_bounds__(256, 4)
k2_gate(const float* __restrict__ Ws)
{
    extern __shared__ float sp[];  // [2][6][34][35] = 14280 floats
    __shared__ float s_ws[54];
    __shared__ double s_redA[8], s_redB[8];

    const int o = blockIdx.x, b = blockIdx.y, dz = blockIdx.z;
    const int tid = threadIdx.x;
    const int obase = b*CO + o;

    if (tid < 54) s_ws[tid] = Ws[tid];
    for (int idx = tid; idx < 2*S2CH; idx += 256) sp[idx] = 0.f;
    __syncthreads();
    #pragma unroll 1
    for (int ch = 0; ch < 2; ch++) {
        #pragma unroll 1
        for (int dd = 0; dd < 6; dd++) {
            int dg = dz*4 + dd - 1;
            if (dg < 0 || dg > 15) continue;
            const float* src = g_pooled + (obase*2 + ch)*PLANE + dg*NPIX;
            float* dstp = sp + ch*S2CH + dd*S2PL + S2ST + 1;
            #pragma unroll
            for (int idx = tid; idx < 1024; idx += 256) {
                int r2 = idx >> 5, cc = idx & 31;
                dstp[r2*S2ST + cc] = src[idx];
            }
        }
    }
    __syncthreads();

    const int dl = tid >> 6;
    const int u  = (tid >> 1) & 31;
    const int vh = (tid & 1) * 16;
    float acc[16];
    #pragma unroll
    for (int v = 0; v < 16; v++) acc[v] = 0.f;
    #pragma unroll 1
    for (int ch = 0; ch < 2; ch++) {
        #pragma unroll
        for (int kd = 0; kd < 3; kd++) {
            #pragma unroll
            for (int kh = 0; kh < 3; kh++) {
                const float* xr = sp + ch*S2CH + (dl+kd)*S2PL + (u+kh)*S2ST + vh;
                float xx[18];
                #pragma unroll
                for (int j = 0; j < 18; j++) xx[j] = xr[j];
                const float* wp = s_ws + ch*27 + kd*9 + kh*3;
                float w0 = wp[0], w1 = wp[1], w2 = wp[2];
                #pragma unroll
                for (int v = 0; v < 16; v++)
                    acc[v] += w0*xx[v] + w1*xx[v+1] + w2*xx[v+2];
            }
        }
    }
    double s = 0.0, s2 = 0.0;
    float* gout = g_gate + obase*PLANE + (dz*4 + dl)*NPIX + u*32 + vh;
    #pragma unroll
    for (int v = 0; v < 16; v++) {
        gout[v] = acc[v];
        double dv = (double)acc[v];
        s += dv; s2 += dv*dv;
    }
    #pragma unroll
    for (int off = 16; off > 0; off >>= 1) {
        s  += __shfl_down_sync(0xffffffffu, s,  off);
        s2 += __shfl_down_sync(0xffffffffu, s2, off);
    }
    int w = tid >> 5;
    if ((tid & 31) == 0) { s_redA[w] = s; s_redB[w] = s2; }
    __syncthreads();
    if (tid < 32) {
        double a = (tid < 8) ? s_redA[tid] : 0.0;
        double bq = (tid < 8) ? s_redB[tid] : 0.0;
        #pragma unroll
        for (int off = 4; off > 0; off >>= 1) {
            a  += __shfl_down_sync(0xffffffffu, a,  off);
            bq += __shfl_down_sync(0xffffffffu, bq, off);
        }
        if (tid == 0) {
            g_part2[(o*NB + b)*4 + dz] = a;
            g_part2[CO*NB*4 + (o*NB + b)*4 + dz] = bq;
        }
    }
}

// ---------------------------------------------------------------------------
// K3: BN-affine (from g_part2) + (1+sigmoid)*preroute + LayerNorm
// ---------------------------------------------------------------------------
extern "C" __global__ void __launch_bounds__(512)
k3_finalize(const float* __restrict__ bng, const float* __restrict__ bnb,
            const float* __restrict__ lng, const float* __restrict__ lnb,
            float* __restrict__ out)
{
    __shared__ float s_red[16];
    __shared__ float sh_a, sh_ofs;
    const int o = blockIdx.x, b = blockIdx.y;
    const int tid = threadIdx.x;
    const int base = (b*CO + o)*PLANE;

    if (tid < 32) {
        double s = 0.0, s2 = 0.0;
        #pragma unroll
        for (int j = 0; j < 4; j++) {
            s  += g_part2[o*NB*4 + tid*4 + j];
            s2 += g_part2[CO*NB*4 + o*NB*4 + tid*4 + j];
        }
        #pragma unroll
        for (int off = 16; off > 0; off >>= 1) {
            s  += __shfl_down_sync(0xffffffffu, s,  off);
            s2 += __shfl_down_sync(0xffffffffu, s2, off);
        }
        if (tid == 0) {
            double n = (double)NB * PLANE;
            double mu = s / n;
            double var = s2 / n - mu*mu;
            float rstd = (float)(1.0 / sqrt(var + 1e-5));
            float a = bng[0] * rstd;
            sh_a = a;
            sh_ofs = bnb[0] - (float)mu * a;
        }
    }
    __syncthreads();
    const float a = sh_a, ofs = sh_ofs;

    float x[32];
    float s = 0.f;
    #pragma unroll
    for (int i = 0; i < 32; i++) {
        int idx = tid + i*512;
        float g = g_gate[base + idx];
        float z = g*a + ofs;
        float sg = 1.f / (1.f + expf(-z));
        float val = g_preroute[base + idx] * (1.f + sg);
        x[i] = val; s += val;
    }
    #pragma unroll
    for (int off = 16; off > 0; off >>= 1) s += __shfl_down_sync(0xffffffffu, s, off);
    int w = tid >> 5;
    if ((tid & 31) == 0) s_red[w] = s;
    __syncthreads();
    if (tid < 32) {
        float t = (tid < 16) ? s_red[tid] : 0.f;
        #pragma unroll
        for (int off = 8; off > 0; off >>= 1) t += __shfl_down_sync(0xffffffffu, t, off);
        if (tid == 0) s_red[0] = t;
    }
    __syncthreads();
    float m = s_red[0] * (1.f/16384.f);
    __syncthreads();

    float v = 0.f;
    #pragma unroll
    for (int i = 0; i < 32; i++) { float dd = x[i] - m; v += dd*dd; }
    #pragma unroll
    for (int off = 16; off > 0; off >>= 1) v += __shfl_down_sync(0xffffffffu, v, off);
    if ((tid & 31) == 0) s_red[w] = v;
    __syncthreads();
    if (tid < 32) {
        float t = (tid < 16) ? s_red[tid] : 0.f;
        #pragma unroll
        for (int off = 8; off > 0; off >>= 1) t += __shfl_down_sync(0xffffffffu, t, off);
        if (tid == 0) s_red[0] = t;
    }
    __syncthreads();
    float rstd = rsqrtf(s_red[0]*(1.f/16384.f) + 1e-5f);

    float* op = out + (o*NB + b)*PLANE;
    #pragma unroll
    for (int i = 0; i < 32; i++) {
        int idx = tid + i*512;
        op[idx] = (x[i] - m)*rstd*lng[idx] + lnb[idx];
    }
}

// ---------------------------------------------------------------------------
extern "C" void kernel_launch(void* const* d_in, const int* in_sizes, int n_in,
                              void* d_out, int out_size)
{
    const float* caps = (const float*)d_in[0];
    const float* Wt   = (const float*)d_in[1];
    const float* bt   = (const float*)d_in[2];
    const float* Wv   = (const float*)d_in[3];
    const float* bv   = (const float*)d_in[4];
    const float* Ws   = (const float*)d_in[5];
    const float* bng  = (const float*)d_in[6];
    const float* bnb  = (const float*)d_in[7];
    const float* lng  = (const float*)d_in[8];
    const float* lnb  = (const float*)d_in[9];
    float* out = (float*)d_out;

    const int smem0  = DI*34*34 * 4;               // 73984
    const int smem1a = 128*4 + 2*128*AB_ST*2;      // 78336
    const int smem2  = 2*S2CH * 4;                 // 57120
    cudaFuncSetAttribute(k0_prep,  cudaFuncAttributeMaxDynamicSharedMemorySize, smem0);
    cudaFuncSetAttribute(k1a_gemm, cudaFuncAttributeMaxDynamicSharedMemorySize, smem1a);
    cudaFuncSetAttribute(k2_gate,  cudaFuncAttributeMaxDynamicSharedMemorySize, smem2);

    k0_prep<<<NB + 1, 1024, smem0>>>(caps, Wt);
    k1a_gemm<<<dim3(CO, NB, 8), 256, smem1a>>>(bt);
    k1b_route<<<dim3(CO, NB, 4), 256>>>(Wv, bv);
    k2_gate<<<dim3(CO, NB, 4), 256, smem2>>>(Ws);
    k3_finalize<<<dim3(CO, NB), 512>>>(bng, bnb, lng, lnb, out);
}

// round 16
// speedup vs baseline: 1.2253x; 1.0888x over previous
#include <cuda_runtime.h>
#include <cuda_fp16.h>
#include <math.h>

#define NB 32
#define CI 8
#define CO 8
#define KR 4
#define DI 16
#define DOUT 16
#define SS 32
#define NPIX 1024
#define PLANE (DOUT*NPIX)   // 16384

#define AB_ST 152           // smem row stride (halves); 76 words = 12 mod 32 -> conflict-free

#define S2ST 35             // K2 smem row stride
#define S2PL (34*S2ST)      // 1190
#define S2CH (4*S2PL)       // 4760 (4 halo planes)

typedef unsigned long long u64;
typedef unsigned int u32;

// ---------------- scratch (static device globals; no allocation) -------------
__device__ float g_pooled[NB*CO*2*PLANE];    // 33.5 MB
__device__ float g_preroute[NB*CO*PLANE];    // 16.8 MB
__device__ float g_gate[NB*CO*PLANE];        // 16.8 MB
__device__ __half g_votes[NB*CO*128*NPIX];   // [b][o][d][ci][pix] 67 MB (fp16)
__device__ double g_part3[2*CO*NB*8];        // BN partials per (o,b,dz)
__device__ __half g_Xh[NB*NPIX*144];         // [b][pix][Xh]  9.4 MB
__device__ __half g_W2[CO*128*288];          // [o][m][Wh(144)|Wl(144)]

// ---------------- helpers ----------------------------------------------------
__device__ __forceinline__ void ffma2(u64& d, const u64 a, const u64 b) {
    asm("fma.rn.f32x2 %0, %1, %2, %0;" : "+l"(d) : "l"(a), "l"(b));
}
__device__ __forceinline__ u64 pack2(float x, float y) {
    u64 r; asm("mov.b64 %0, {%1,%2};" : "=l"(r) : "f"(x), "f"(y)); return r;
}
__device__ __forceinline__ float2 unpack2(u64 v) {
    float2 r; asm("mov.b64 {%0,%1}, %2;" : "=f"(r.x), "=f"(r.y) : "l"(v)); return r;
}
__device__ __forceinline__ void mma_f16(float* d, const u32* a, const u32* b) {
    asm volatile(
        "mma.sync.aligned.m16n8k16.row.col.f32.f16.f16.f32 "
        "{%0,%1,%2,%3}, {%4,%5,%6,%7}, {%8,%9}, {%0,%1,%2,%3};"
        : "+f"(d[0]), "+f"(d[1]), "+f"(d[2]), "+f"(d[3])
        : "r"(a[0]), "r"(a[1]), "r"(a[2]), "r"(a[3]), "r"(b[0]), "r"(b[1]));
}

// ---------------------------------------------------------------------------
// K0: build fp16 split operands.  blocks 0..31: X for batch b; block 32: W.
// ---------------------------------------------------------------------------
extern "C" __global__ void __launch_bounds__(1024)
k0_prep(const float* __restrict__ caps, const float* __restrict__ Wt)
{
    extern __shared__ float sp[];   // 16*34*34 = 18496
    const int tid = threadIdx.x;
    if (blockIdx.x < NB) {
        const int b = blockIdx.x;
        for (int idx = tid; idx < DI*1156; idx += 1024) {
            int ch = idx / 1156, rem = idx % 1156;
            int pr = rem / 34, pc = rem % 34;
            float v = 0.f;
            if (pr >= 1 && pr <= SS && pc >= 1 && pc <= SS)
                v = caps[((b*DI + ch)*SS + (pr-1))*SS + (pc-1)];
            sp[idx] = v;
        }
        __syncthreads();
        for (int idx = tid; idx < NPIX*144; idx += 1024) {
            int pix = idx / 144, s = idx % 144;
            int cin = s / 9, tap = s % 9;
            int dy = tap / 3, dx = tap % 3;
            int prow = pix >> 5, pcol = pix & 31;
            float v = sp[cin*1156 + (prow+dy)*34 + (pcol+dx)];
            g_Xh[((u64)b*NPIX + pix)*144 + s] = __float2half(v);
        }
    } else {
        for (int idx = tid; idx < CO*128*144; idx += 1024) {
            int s = idx % 144, m = (idx/144) & 127, o = idx/(144*128);
            int c = m >> 4, d = m & 15;
            float v = Wt[(((c*CO + o)*DOUT + d)*144) + s];
            __half h = __float2half(v);
            __half l = __float2half(v - __half2float(h));
            __half* dst = g_W2 + (o*128 + m)*288 + s;
            dst[0]   = h;      // Wh
            dst[144] = l;      // Wl
        }
    }
}

// ---------------------------------------------------------------------------
// K1a: fp16 2-term split conv-GEMM (Wh*Xh + Wl*Xh), tile 128m x 128pix,
// K=144/term.  grid (o=8, b=32, pt=8), 256 threads, 78.3 KB smem,
// 2 blocks/SM.  B (Xh) staged once per tile; A staged per term.
// Writes votes (+bias) as fp16 half2 from accum regs, coalesced STG.32.
// ---------------------------------------------------------------------------
extern "C" __global__ void __launch_bounds__(256, 2)
k1a_gemm(const float* __restrict__ bt)
{
    extern __shared__ float sm[];
    float* s_bias = sm;                        // 128 floats
    __half* s_A = (__half*)(sm + 128);         // 128 x AB_ST
    __half* s_B = s_A + 128*AB_ST;             // 128 x AB_ST

    const int o = blockIdx.x, b = blockIdx.y, pt = blockIdx.z;
    const int tb = pt*128;
    const int tid  = threadIdx.x;
    const int w    = tid >> 5, lane = tid & 31;
    const int wm   = w & 3,  wn = w >> 2;       // warp tile: rows wm*32, cols wn*64
    const int g    = lane >> 2, t = lane & 3;
    const int obase = b*CO + o;

    if (tid < 128)
        s_bias[tid] = bt[(((tid >> 4)*CO + o)*DOUT) + (tid & 15)];

    float acc[2][8][4];
    #pragma unroll
    for (int mi = 0; mi < 2; mi++)
        #pragma unroll
        for (int nj = 0; nj < 8; nj++)
            #pragma unroll
            for (int e = 0; e < 4; e++) acc[mi][nj][e] = 0.f;

    #pragma unroll 1
    for (int seg = 0; seg < 2; seg++) {
        const int aoff = seg*144;              // Wh then Wl
        #pragma unroll
        for (int i = tid; i < 2304; i += 256) {
            int m = i / 18, j = i % 18;
            float4 v = ((const float4*)(g_W2 + (o*128 + m)*288 + aoff))[j];
            ((float4*)((char*)s_A + m*(AB_ST*2)))[j] = v;
        }
        if (seg == 0) {
            #pragma unroll
            for (int i = tid; i < 2304; i += 256) {
                int pr = i / 18, j = i % 18;
                float4 v = ((const float4*)(g_Xh + ((u64)b*NPIX + tb + pr)*144))[j];
                ((float4*)((char*)s_B + pr*(AB_ST*2)))[j] = v;
            }
        }
        __syncthreads();
        #pragma unroll
        for (int ks = 0; ks < 9; ks++) {
            const int kb = ks*16;    // fp16 units
            u32 afr[2][4];
            #pragma unroll
            for (int mi = 0; mi < 2; mi++) {
                const __half* ar = s_A + (wm*32 + mi*16 + g)*AB_ST + kb + 2*t;
                afr[mi][0] = *(const u32*)(ar);
                afr[mi][1] = *(const u32*)(ar + 8*AB_ST);
                afr[mi][2] = *(const u32*)(ar + 8);
                afr[mi][3] = *(const u32*)(ar + 8*AB_ST + 8);
            }
            u32 bfr[8][2];
            #pragma unroll
            for (int nj = 0; nj < 8; nj++) {
                const __half* br = s_B + (wn*64 + nj*8 + g)*AB_ST + kb + 2*t;
                bfr[nj][0] = *(const u32*)(br);
                bfr[nj][1] = *(const u32*)(br + 8);
            }
            #pragma unroll
            for (int mi = 0; mi < 2; mi++)
                #pragma unroll
                for (int nj = 0; nj < 8; nj++)
                    mma_f16(acc[mi][nj], afr[mi], bfr[nj]);
        }
        __syncthreads();
    }

    // write votes (+bias) as half2: [b][o][d][ci][pix], STG.32 (pix pairs)
    #pragma unroll
    for (int mi = 0; mi < 2; mi++) {
        #pragma unroll
        for (int e2 = 0; e2 < 2; e2++) {
            int m = wm*32 + mi*16 + g + e2*8;
            int ci = m >> 4, d = m & 15;
            float bias = s_bias[m];
            __half* rowp = g_votes + (((u64)obase*16 + d)*8 + ci)*NPIX;
            #pragma unroll
            for (int nj = 0; nj < 8; nj++) {
                int pix = tb + wn*64 + nj*8 + 2*t;
                __half2 hv = __floats2half2_rn(acc[mi][nj][e2*2] + bias,
                                               acc[mi][nj][e2*2+1] + bias);
                *(__half2*)(rowp + pix) = hv;
            }
        }
    }
}

// ---------------------------------------------------------------------------
// K1b: routing epilogue (fp16 votes).  grid (o=8, b=32, pz=4), 256 threads.
// ---------------------------------------------------------------------------
extern "C" __global__ void __launch_bounds__(256)
k1b_route(const float* __restrict__ Wv, const float* __restrict__ bv)
{
    __shared__ u64 s_wp[128];
    __shared__ u64 s_bvp[16];
    const int o = blockIdx.x, b = blockIdx.y, pz = blockIdx.z;
    const int tid = threadIdx.x;
    const int obase = b*CO + o;

    if (tid < 128) {
        int c2 = tid >> 4, ci = (tid >> 1) & 7, h = tid & 1;
        s_wp[tid] = pack2(Wv[o*256 + ((2*h)*8 + c2)*8 + ci],
                          Wv[o*256 + ((2*h+1)*8 + c2)*8 + ci]);
    }
    if (tid < 16) {
        int c2 = tid >> 1, h = tid & 1;
        s_bvp[tid] = pack2(bv[o*32 + (2*h)*8 + c2], bv[o*32 + (2*h+1)*8 + c2]);
    }
    __syncthreads();

    #pragma unroll 1
    for (int i = 0; i < 16; i++) {
        int idx = i*256 + tid;           // 0..4095
        int pix = pz*256 + (idx & 255);
        int d   = idx >> 8;
        const __half* vb = g_votes + ((u64)obase*16 + d)*8*NPIX + pix;
        u64 vd[8];
        #pragma unroll
        for (int ci = 0; ci < 8; ci++) {
            float v = __half2float(vb[ci*NPIX]);
            vd[ci] = pack2(v, v);
        }
        float vmax = -3.0e38f, vsum = 0.f, num = 0.f, den = 0.f;
        #pragma unroll
        for (int c2 = 0; c2 < 8; c2++) {
            u64 a0 = s_bvp[c2*2 + 0];
            u64 a1 = s_bvp[c2*2 + 1];
            #pragma unroll
            for (int ci = 0; ci < 8; ci++) {
                ffma2(a0, vd[ci], s_wp[(c2*8 + ci)*2 + 0]);
                ffma2(a1, vd[ci], s_wp[(c2*8 + ci)*2 + 1]);
            }
            float2 p0 = unpack2(a0), p1 = unpack2(a1);
            float v0 = p0.x, v1 = p0.y, v2 = p1.x, v3 = p1.y;
            vmax = fmaxf(vmax, fmaxf(fmaxf(v0, v1), fmaxf(v2, v3)));
            float sum4 = (v0 + v1) + (v2 + v3);
            vsum += sum4;
            float mu = 0.25f*sum4;
            float d0 = v0-mu, d1 = v1-mu, d2 = v2-mu, d3 = v3-mu;
            float var = 0.25f*((d0*d0 + d1*d1) + (d2*d2 + d3*d3));
            float rr = rsqrtf(var);
            num += rr*mu;
            den += rr;
        }
        g_pooled[(obase*2 + 0)*PLANE + d*NPIX + pix] = vmax;
        g_pooled[(obase*2 + 1)*PLANE + d*NPIX + pix] = vsum*(1.f/32.f);
        g_preroute[obase*PLANE + d*NPIX + pix] = num/den;
    }
}

// ---------------------------------------------------------------------------
// K2: spatial gate 3x3x3 conv + BN partials.  dz=8 tiling: 2 output planes
// from 4 halo planes.  grid (o=8, b=32, dz=8), 256 threads, 38.1 KB smem
// -> 4 blocks/SM.  Thread = (dl, u, vq): 8 outputs.
// ---------------------------------------------------------------------------
extern "C" __global__ void __launch_bounds__(256, 4)
k2_gate(const float* __restrict__ Ws)
{
    extern __shared__ float sp[];  // [2][4][34][35] = 9520 floats
    __shared__ float s_ws[54];
    __shared__ double s_redA[8], s_redB[8];

    const int o = blockIdx.x, b = blockIdx.y, dz = blockIdx.z;
    const int tid = threadIdx.x;
    const int obase = b*CO + o;

    if (tid < 54) s_ws[tid] = Ws[tid];
    for (int idx = tid; idx < 2*S2CH; idx += 256) sp[idx] = 0.f;
    __syncthreads();
    #pragma unroll 1
    for (int ch = 0; ch < 2; ch++) {
        #pragma unroll 1
        for (int dd = 0; dd < 4; dd++) {
            int dg = dz*2 + dd - 1;
            if (dg < 0 || dg > 15) continue;
            const float* src = g_pooled + (obase*2 + ch)*PLANE + dg*NPIX;
            float* dstp = sp + ch*S2CH + dd*S2PL + S2ST + 1;
            #pragma unroll
            for (int idx = tid; idx < 1024; idx += 256) {
                int r2 = idx >> 5, cc = idx & 31;
                dstp[r2*S2ST + cc] = src[idx];
            }
        }
    }
    __syncthreads();

    const int dl = tid >> 7;          // 0..1 local output d
    const int u  = (tid >> 2) & 31;   // output row
    const int vq = (tid & 3) * 8;     // v quarter
    float acc[8];
    #pragma unroll
    for (int v = 0; v < 8; v++) acc[v] = 0.f;
    #pragma unroll 1
    for (int ch = 0; ch < 2; ch++) {
        #pragma unroll
        for (int kd = 0; kd < 3; kd++) {
            #pragma unroll
            for (int kh = 0; kh < 3; kh++) {
                const float* xr = sp + ch*S2CH + (dl+kd)*S2PL + (u+kh)*S2ST + vq;
                float xx[10];
                #pragma unroll
                for (int j = 0; j < 10; j++) xx[j] = xr[j];
                const float* wp = s_ws + ch*27 + kd*9 + kh*3;
                float w0 = wp[0], w1 = wp[1], w2 = wp[2];
                #pragma unroll
                for (int v = 0; v < 8; v++)
                    acc[v] += w0*xx[v] + w1*xx[v+1] + w2*xx[v+2];
            }
        }
    }
    double s = 0.0, s2 = 0.0;
    float* gout = g_gate + obase*PLANE + (dz*2 + dl)*NPIX + u*32 + vq;
    #pragma unroll
    for (int v = 0; v < 8; v++) {
        gout[v] = acc[v];
        double dv = (double)acc[v];
        s += dv; s2 += dv*dv;
    }
    #pragma unroll
    for (int off = 16; off > 0; off >>= 1) {
        s  += __shfl_down_sync(0xffffffffu, s,  off);
        s2 += __shfl_down_sync(0xffffffffu, s2, off);
    }
    int w = tid >> 5;
    if ((tid & 31) == 0) { s_redA[w] = s; s_redB[w] = s2; }
    __syncthreads();
    if (tid < 32) {
        double a = (tid < 8) ? s_redA[tid] : 0.0;
        double bq = (tid < 8) ? s_redB[tid] : 0.0;
        #pragma unroll
        for (int off = 4; off > 0; off >>= 1) {
            a  += __shfl_down_sync(0xffffffffu, a,  off);
            bq += __shfl_down_sync(0xffffffffu, bq, off);
        }
        if (tid == 0) {
            g_part3[(o*NB + b)*8 + dz] = a;
            g_part3[CO*NB*8 + (o*NB + b)*8 + dz] = bq;
        }
    }
}

// ---------------------------------------------------------------------------
// K3: BN-affine (from g_part3) + (1+sigmoid)*preroute + LayerNorm
// ---------------------------------------------------------------------------
extern "C" __global__ void __launch_bounds__(512)
k3_finalize(const float* __restrict__ bng, const float* __restrict__ bnb,
            const float* __restrict__ lng, const float* __restrict__ lnb,
            float* __restrict__ out)
{
    __shared__ float s_red[16];
    __shared__ float sh_a, sh_ofs;
    const int o = blockIdx.x, b = blockIdx.y;
    const int tid = threadIdx.x;
    const int base = (b*CO + o)*PLANE;

    if (tid < 32) {
        double s = 0.0, s2 = 0.0;
        #pragma unroll
        for (int j = 0; j < 8; j++) {
            s  += g_part3[o*NB*8 + tid*8 + j];
            s2 += g_part3[CO*NB*8 + o*NB*8 + tid*8 + j];
        }
        #pragma unroll
        for (int off = 16; off > 0; off >>= 1) {
            s  += __shfl_down_sync(0xffffffffu, s,  off);
            s2 += __shfl_down_sync(0xffffffffu, s2, off);
        }
        if (tid == 0) {
            double n = (double)NB * PLANE;
            double mu = s / n;
            double var = s2 / n - mu*mu;
            float rstd = (float)(1.0 / sqrt(var + 1e-5));
            float a = bng[0] * rstd;
            sh_a = a;
            sh_ofs = bnb[0] - (float)mu * a;
        }
    }
    __syncthreads();
    const float a = sh_a, ofs = sh_ofs;

    float x[32];
    float s = 0.f;
    #pragma unroll
    for (int i = 0; i < 32; i++) {
        int idx = tid + i*512;
        float g = g_gate[base + idx];
        float z = g*a + ofs;
        float sg = 1.f / (1.f + expf(-z));
        float val = g_preroute[base + idx] * (1.f + sg);
        x[i] = val; s += val;
    }
    #pragma unroll
    for (int off = 16; off > 0; off >>= 1) s += __shfl_down_sync(0xffffffffu, s, off);
    int w = tid >> 5;
    if ((tid & 31) == 0) s_red[w] = s;
    __syncthreads();
    if (tid < 32) {
        float t = (tid < 16) ? s_red[tid] : 0.f;
        #pragma unroll
        for (int off = 8; off > 0; off >>= 1) t += __shfl_down_sync(0xffffffffu, t, off);
        if (tid == 0) s_red[0] = t;
    }
    __syncthreads();
    float m = s_red[0] * (1.f/16384.f);
    __syncthreads();

    float v = 0.f;
    #pragma unroll
    for (int i = 0; i < 32; i++) { float dd = x[i] - m; v += dd*dd; }
    #pragma unroll
    for (int off = 16; off > 0; off >>= 1) v += __shfl_down_sync(0xffffffffu, v, off);
    if ((tid & 31) == 0) s_red[w] = v;
    __syncthreads();
    if (tid < 32) {
        float t = (tid < 16) ? s_red[tid] : 0.f;
        #pragma unroll
        for (int off = 8; off > 0; off >>= 1) t += __shfl_down_sync(0xffffffffu, t, off);
        if (tid == 0) s_red[0] = t;
    }
    __syncthreads();
    float rstd = rsqrtf(s_red[0]*(1.f/16384.f) + 1e-5f);

    float* op = out + (o*NB + b)*PLANE;
    #pragma unroll
    for (int i = 0; i < 32; i++) {
        int idx = tid + i*512;
        op[idx] = (x[i] - m)*rstd*lng[idx] + lnb[idx];
    }
}

// ---------------------------------------------------------------------------
extern "C" void kernel_launch(void* const* d_in, const int* in_sizes, int n_in,
                              void* d_out, int out_size)
{
    const float* caps = (const float*)d_in[0];
    const float* Wt   = (const float*)d_in[1];
    const float* bt   = (const float*)d_in[2];
    const float* Wv   = (const float*)d_in[3];
    const float* bv   = (const float*)d_in[4];
    const float* Ws   = (const float*)d_in[5];
    const float* bng  = (const float*)d_in[6];
    const float* bnb  = (const float*)d_in[7];
    const float* lng  = (const float*)d_in[8];
    const float* lnb  = (const float*)d_in[9];
    float* out = (float*)d_out;

    const int smem0  = DI*34*34 * 4;               // 73984
    const int smem1a = 128*4 + 2*128*AB_ST*2;      // 78336
    const int smem2  = 2*S2CH * 4;                 // 38080
    cudaFuncSetAttribute(k0_prep,  cudaFuncAttributeMaxDynamicSharedMemorySize, smem0);
    cudaFuncSetAttribute(k1a_gemm, cudaFuncAttributeMaxDynamicSharedMemorySize, smem1a);
    cudaFuncSetAttribute(k2_gate,  cudaFuncAttributeMaxDynamicSharedMemorySize, smem2);

    k0_prep<<<NB + 1, 1024, smem0>>>(caps, Wt);
    k1a_gemm<<<dim3(CO, NB, 8), 256, smem1a>>>(bt);
    k1b_route<<<dim3(CO, NB, 4), 256>>>(Wv, bv);
    k2_gate<<<dim3(CO, NB, 8), 256, smem2>>>(Ws);
    k3_finalize<<<dim3(CO, NB), 512>>>(bng, bnb, lng, lnb, out);
}